// round 16
// baseline (speedup 1.0000x reference)
#include <cuda_runtime.h>
#include <cuda_fp16.h>
#include <mma.h>
#include <cstdint>

using namespace nvcuda;

#define NMAX 102400
#define HDIM 512
#define EDIM 128
#define KTOT 640
#define MROWS 128        // dense M tile per CTA
#define KC 64            // K chunk
#define NCH (KTOT / KC)  // 10 chunks per pass
#define NP 128           // N cols per pass (4 passes)
#define STAGES 3
#define A_ST 72          // A row stride (halfs): 64 + 8
#define B_ST 136         // B row stride (halfs): 128 + 8
#define S_ST 36          // epilogue strip stride (floats)
#define THREADS 256      // 8 warps: wm = wid>>2 (2), wn = wid&3 (4)

#define A_BYTES (STAGES * MROWS * A_ST * 2)    // 55296
#define B_BYTES (STAGES * KC * B_ST * 2)       // 52224
#define SMEM_BYTES (A_BYTES + B_BYTES)         // 107520 (strips 73728 reuse)

// Precomputed fp16 operands (device-global scratch — allowed)
__device__ __half g_hin[(size_t)NMAX * KTOT];  // fused [hist_enc | emb]
__device__ __half g_wm[KTOT * HDIM];

__device__ __forceinline__ uint32_t smem_u32(const void* p) {
    uint32_t a;
    asm("{ .reg .u64 t; cvta.to.shared.u64 t, %1; cvt.u32.u64 %0, t; }" : "=r"(a) : "l"(p));
    return a;
}
__device__ __forceinline__ void cp_async16(uint32_t saddr, const void* gptr) {
    asm volatile("cp.async.cg.shared.global [%0], [%1], 16;" :: "r"(saddr), "l"(gptr));
}
#define CP_COMMIT() asm volatile("cp.async.commit_group;" ::: "memory")
#define CP_WAIT0()  asm volatile("cp.async.wait_group 0;" ::: "memory")
#define CP_WAIT1()  asm volatile("cp.async.wait_group 1;" ::: "memory")

// ---- prekernel 0: zero the output (atomicMax target, relu output >= 0) -----
__global__ void init_out_kernel(float* __restrict__ out) {
    reinterpret_cast<float4*>(out)[blockIdx.x * 256 + threadIdx.x] =
        make_float4(0.f, 0.f, 0.f, 0.f);
}

// ---- prekernel 1: Wm fp32 -> fp16 ------------------------------------------
__global__ void conv_wm_kernel(const float* __restrict__ Wm) {
    const int idx = blockIdx.x * 256 + threadIdx.x;   // 81920 float4s
    const float4 v = reinterpret_cast<const float4*>(Wm)[idx];
    __half2 h[2] = {__floats2half2_rn(v.x, v.y), __floats2half2_rn(v.z, v.w)};
    *reinterpret_cast<uint2*>(g_wm + 4 * (size_t)idx) = *reinterpret_cast<uint2*>(h);
}

// ---- prekernel 2: build fused H_in fp16 ------------------------------------
__global__ void build_hin_kernel(const float* __restrict__ hist_enc,
                                 const float* __restrict__ hist_pos,
                                 const int*   __restrict__ sse,
                                 const float* __restrict__ Ws,
                                 const float* __restrict__ bs) {
    const int g = blockIdx.x;
    const int start = sse[g];
    const int cnt = sse[g + 1] - start;
    const int tid = threadIdx.x;
    const float ax = hist_pos[2 * start + 0];
    const float ay = hist_pos[2 * start + 1];

    for (int idx = tid; idx < cnt * (HDIM / 4); idx += 256) {
        const int r = idx >> 7, c4 = idx & 127;
        const float4 v = *(const float4*)(hist_enc + (size_t)(start + r) * HDIM + 4 * c4);
        __half2 h[2] = {__floats2half2_rn(v.x, v.y), __floats2half2_rn(v.z, v.w)};
        *reinterpret_cast<uint2*>(g_hin + (size_t)(start + r) * KTOT + 4 * c4) =
            *reinterpret_cast<uint2*>(h);
    }
    for (int idx = tid; idx < cnt * (EDIM / 4); idx += 256) {
        const int r = idx >> 5, c4 = idx & 31;
        const int e = 4 * c4;
        const float rx = hist_pos[2 * (start + r) + 0] - ax;
        const float ry = hist_pos[2 * (start + r) + 1] - ay;
        const float v0 = fmaxf(fmaf(rx, Ws[e+0], fmaf(ry, Ws[EDIM+e+0], bs[e+0])), 0.f);
        const float v1 = fmaxf(fmaf(rx, Ws[e+1], fmaf(ry, Ws[EDIM+e+1], bs[e+1])), 0.f);
        const float v2 = fmaxf(fmaf(rx, Ws[e+2], fmaf(ry, Ws[EDIM+e+2], bs[e+2])), 0.f);
        const float v3 = fmaxf(fmaf(rx, Ws[e+3], fmaf(ry, Ws[EDIM+e+3], bs[e+3])), 0.f);
        __half2 h[2] = {__floats2half2_rn(v0, v1), __floats2half2_rn(v2, v3)};
        *reinterpret_cast<uint2*>(g_hin + (size_t)(start + r) * KTOT + HDIM + e) =
            *reinterpret_cast<uint2*>(h);
    }
}

// ---- main: dense fp16 GEMM (3-stage pipeline) + tile-local segment max -----
__global__ __launch_bounds__(THREADS, 2)
void gemm_pool_kernel(const int* __restrict__ sse,
                      const float* __restrict__ bm,
                      float* __restrict__ out,
                      int num_groups, int ntotal)
{
    extern __shared__ char sm[];
    __half* As = (__half*)sm;                  // [stage][128][A_ST]
    __half* Bs = (__half*)(sm + A_BYTES);      // [stage][KC][B_ST]
    float*  smf = (float*)sm;                  // epilogue strips

    const int tid  = threadIdx.x;
    const int wid  = tid >> 5;
    const int wm   = wid >> 2;                 // 0..1
    const int wn   = wid & 3;                  // 0..3
    const int row0 = blockIdx.x * MROWS;
    const int rmax = min(MROWS, ntotal - row0);

    // Group containing row0 (binary search)
    int g0;
    {
        int lo = 0, hi = num_groups - 1;
        while (lo < hi) {
            const int mid = (lo + hi + 1) >> 1;
            if (sse[mid] <= row0) lo = mid; else hi = mid - 1;
        }
        g0 = lo;
    }

    auto issue_A = [&](int k0, int buf) {
        const uint32_t sb = smem_u32(As + buf * MROWS * A_ST);
        const __half* gp = g_hin + (size_t)row0 * KTOT + k0;
        #pragma unroll
        for (int q = 0; q < 4; q++) {
            const int u = tid + THREADS * q;   // 1024 units of 8 halfs
            const int r = u >> 3, c = u & 7;
            if (r < rmax)
                cp_async16(sb + (uint32_t)(r * A_ST + 8 * c) * 2,
                           gp + (size_t)r * KTOT + 8 * c);
        }
    };
    auto issue_B = [&](int k0, int n0, int buf) {
        const uint32_t sb = smem_u32(Bs + buf * KC * B_ST);
        const __half* gp = g_wm + (size_t)k0 * HDIM + n0;
        #pragma unroll
        for (int j = 0; j < 4; j++) {
            const int u = tid + THREADS * j;   // 1024 units of 8 halfs
            const int r = u >> 4, c = u & 15;
            cp_async16(sb + (uint32_t)(r * B_ST + 8 * c) * 2,
                       gp + (size_t)r * HDIM + 8 * c);
        }
    };

    for (int pass = 0; pass < 4; pass++) {
        const int n0 = pass * NP;

        if (rmax < MROWS) {   // pad rows must be zero (tail tile only)
            for (int idx = tid; idx < A_BYTES / 16; idx += THREADS)
                reinterpret_cast<uint4*>(As)[idx] = make_uint4(0, 0, 0, 0);
        }
        __syncthreads();      // strips of previous pass fully read

        wmma::fragment<wmma::accumulator, 16, 16, 16, float> acc[4][2];
        #pragma unroll
        for (int i = 0; i < 4; i++) {
            wmma::fill_fragment(acc[i][0], 0.0f);
            wmma::fill_fragment(acc[i][1], 0.0f);
        }

        // Prologue: chunks 0,1 in flight
        issue_A(0, 0);  issue_B(0, n0, 0);  CP_COMMIT();
        issue_A(KC, 1); issue_B(KC, n0, 1); CP_COMMIT();

        for (int i = 0; i < NCH; i++) {
            const int buf = i % STAGES;
            if (i + 1 < NCH) CP_WAIT1();   // chunk i landed, i+1 still flying
            else             CP_WAIT0();
            __syncthreads();
            if (i + 2 < NCH) {             // top up the pipeline
                issue_A((i + 2) * KC, (i + 2) % STAGES);
                issue_B((i + 2) * KC, n0, (i + 2) % STAGES);
                CP_COMMIT();
            }

            const __half* Ab = As + buf * MROWS * A_ST;
            const __half* Bb = Bs + buf * KC * B_ST;
            #pragma unroll
            for (int kk = 0; kk < KC; kk += 16) {
                wmma::fragment<wmma::matrix_a, 16, 16, 16, __half,
                               wmma::row_major> fa[4];
                #pragma unroll
                for (int i2 = 0; i2 < 4; i2++)
                    wmma::load_matrix_sync(fa[i2],
                        Ab + (64 * wm + 16 * i2) * A_ST + kk, A_ST);
                #pragma unroll
                for (int j = 0; j < 2; j++) {
                    wmma::fragment<wmma::matrix_b, 16, 16, 16, __half,
                                   wmma::row_major> fb;
                    wmma::load_matrix_sync(fb,
                        Bb + kk * B_ST + 32 * wn + 16 * j, B_ST);
                    #pragma unroll
                    for (int i2 = 0; i2 < 4; i2++)
                        wmma::mma_sync(acc[i2][j], fa[i2], fb, acc[i2][j]);
                }
            }
        }

        // ---- epilogue: strips, per-segment column max, store/atomic -------
        __syncthreads();   // mainloop smem dead; strips may overwrite
        float* strip = smf + wn * (MROWS * S_ST);
        #pragma unroll
        for (int i = 0; i < 4; i++) {
            wmma::store_matrix_sync(strip + (64 * wm + 16 * i) * S_ST, acc[i][0],
                                    S_ST, wmma::mem_row_major);
            wmma::store_matrix_sync(strip + (64 * wm + 16 * i) * S_ST + 16,
                                    acc[i][1], S_ST, wmma::mem_row_major);
        }
        __syncthreads();

        if (tid < NP) {
            const int pcol = tid;
            const float* s = smf + (pcol >> 5) * (MROWS * S_ST) + (pcol & 31);
            const float bias = bm[n0 + pcol];
            int g = g0;
            int segbeg = 0;
            int segend = min(sse[g + 1] - row0, rmax);
            const bool beg_cut = (sse[g0] < row0);   // first group truncated?
            float m = -3.4e38f;
            for (int r = 0; r < rmax; r++) {
                m = fmaxf(m, s[r * S_ST]);
                if (r + 1 == segend) {
                    const float val = fmaxf(m + bias, 0.f);
                    float* dst = &out[(size_t)g * HDIM + n0 + pcol];
                    const bool cut = (g == g0 && beg_cut) ||
                                     (sse[g + 1] > row0 + rmax);
                    if (cut)
                        atomicMax((unsigned*)dst, __float_as_uint(val));
                    else
                        *dst = val;
                    g++;
                    segbeg = segend;
                    segend = (g < num_groups) ? min(sse[g + 1] - row0, rmax)
                                              : rmax + 1;
                    m = -3.4e38f;
                }
            }
            (void)segbeg;
        }
        __syncthreads();   // strips read before next pass restages smem
    }
}

extern "C" void kernel_launch(void* const* d_in, const int* in_sizes, int n_in,
                              void* d_out, int out_size)
{
    const float* hist_enc = (const float*)d_in[0];
    const float* hist_pos = (const float*)d_in[1];
    const int*   sse      = (const int*)d_in[2];
    const float* Ws       = (const float*)d_in[3];
    const float* bs       = (const float*)d_in[4];
    const float* Wm       = (const float*)d_in[5];
    const float* bm       = (const float*)d_in[6];
    float* out            = (float*)d_out;

    const int num_groups = in_sizes[2] - 1;
    const int ntotal     = in_sizes[0] / HDIM;
    const int grid       = (ntotal + MROWS - 1) / MROWS;

    cudaFuncSetAttribute(gemm_pool_kernel,
                         cudaFuncAttributeMaxDynamicSharedMemorySize,
                         SMEM_BYTES);

    init_out_kernel<<<(out_size / 4 + 255) / 256, 256>>>(out);
    conv_wm_kernel<<<(KTOT * HDIM / 4) / 256, 256>>>(Wm);
    build_hin_kernel<<<num_groups, 256>>>(hist_enc, hist_pos, sse, Ws, bs);
    gemm_pool_kernel<<<grid, THREADS, SMEM_BYTES>>>(sse, bm, out,
                                                    num_groups, ntotal);
}

// round 17
// speedup vs baseline: 1.0544x; 1.0544x over previous
#include <cuda_runtime.h>
#include <cuda_fp16.h>
#include <mma.h>
#include <cstdint>

using namespace nvcuda;

#define NMAX 102400
#define HDIM 512
#define EDIM 128
#define KTOT 640
#define MROWS 128        // dense M tile per CTA
#define KC 80            // K chunk (640 = 8 x 80)
#define NCH (KTOT / KC)  // 8 chunks per pass
#define NP 128           // N cols per pass (4 passes)
#define A_ST 88          // A row stride (halfs): 80 + 8
#define B_ST 136         // B row stride (halfs): 128 + 8
#define S_ST 36          // epilogue strip stride (floats)
#define THREADS 256      // 8 warps: wm = wid>>2 (2), wn = wid&3 (4)

#define A_BYTES (2 * MROWS * A_ST * 2)         // 45056
#define B_BYTES (2 * KC * B_ST * 2)            // 43520
#define SMEM_BYTES (A_BYTES + B_BYTES)         // 88576 (strips 73728 reuse)

// Precomputed fp16 operands (device-global scratch — allowed)
__device__ __half g_hin[(size_t)NMAX * KTOT];  // fused [hist_enc | emb]
__device__ __half g_wm[KTOT * HDIM];

__device__ __forceinline__ uint32_t smem_u32(const void* p) {
    uint32_t a;
    asm("{ .reg .u64 t; cvta.to.shared.u64 t, %1; cvt.u32.u64 %0, t; }" : "=r"(a) : "l"(p));
    return a;
}
__device__ __forceinline__ void cp_async16(uint32_t saddr, const void* gptr) {
    asm volatile("cp.async.cg.shared.global [%0], [%1], 16;" :: "r"(saddr), "l"(gptr));
}
#define CP_COMMIT() asm volatile("cp.async.commit_group;" ::: "memory")
#define CP_WAIT0()  asm volatile("cp.async.wait_group 0;" ::: "memory")

// ---- prekernel 0: zero the output (atomicMax target, relu output >= 0) -----
__global__ void init_out_kernel(float* __restrict__ out) {
    reinterpret_cast<float4*>(out)[blockIdx.x * 256 + threadIdx.x] =
        make_float4(0.f, 0.f, 0.f, 0.f);
}

// ---- prekernel 1: Wm fp32 -> fp16 ------------------------------------------
__global__ void conv_wm_kernel(const float* __restrict__ Wm) {
    const int idx = blockIdx.x * 256 + threadIdx.x;   // 81920 float4s
    const float4 v = reinterpret_cast<const float4*>(Wm)[idx];
    __half2 h[2] = {__floats2half2_rn(v.x, v.y), __floats2half2_rn(v.z, v.w)};
    *reinterpret_cast<uint2*>(g_wm + 4 * (size_t)idx) = *reinterpret_cast<uint2*>(h);
}

// ---- prekernel 2: build fused H_in fp16 ------------------------------------
__global__ void build_hin_kernel(const float* __restrict__ hist_enc,
                                 const float* __restrict__ hist_pos,
                                 const int*   __restrict__ sse,
                                 const float* __restrict__ Ws,
                                 const float* __restrict__ bs) {
    const int g = blockIdx.x;
    const int start = sse[g];
    const int cnt = sse[g + 1] - start;
    const int tid = threadIdx.x;
    const float ax = hist_pos[2 * start + 0];
    const float ay = hist_pos[2 * start + 1];

    for (int idx = tid; idx < cnt * (HDIM / 4); idx += 256) {
        const int r = idx >> 7, c4 = idx & 127;
        const float4 v = *(const float4*)(hist_enc + (size_t)(start + r) * HDIM + 4 * c4);
        __half2 h[2] = {__floats2half2_rn(v.x, v.y), __floats2half2_rn(v.z, v.w)};
        *reinterpret_cast<uint2*>(g_hin + (size_t)(start + r) * KTOT + 4 * c4) =
            *reinterpret_cast<uint2*>(h);
    }
    for (int idx = tid; idx < cnt * (EDIM / 4); idx += 256) {
        const int r = idx >> 5, c4 = idx & 31;
        const int e = 4 * c4;
        const float rx = hist_pos[2 * (start + r) + 0] - ax;
        const float ry = hist_pos[2 * (start + r) + 1] - ay;
        const float v0 = fmaxf(fmaf(rx, Ws[e+0], fmaf(ry, Ws[EDIM+e+0], bs[e+0])), 0.f);
        const float v1 = fmaxf(fmaf(rx, Ws[e+1], fmaf(ry, Ws[EDIM+e+1], bs[e+1])), 0.f);
        const float v2 = fmaxf(fmaf(rx, Ws[e+2], fmaf(ry, Ws[EDIM+e+2], bs[e+2])), 0.f);
        const float v3 = fmaxf(fmaf(rx, Ws[e+3], fmaf(ry, Ws[EDIM+e+3], bs[e+3])), 0.f);
        __half2 h[2] = {__floats2half2_rn(v0, v1), __floats2half2_rn(v2, v3)};
        *reinterpret_cast<uint2*>(g_hin + (size_t)(start + r) * KTOT + HDIM + e) =
            *reinterpret_cast<uint2*>(h);
    }
}

// ---- main: dense fp16 GEMM (2-stage, KC=80) + tile-local segment max -------
__global__ __launch_bounds__(THREADS, 2)
void gemm_pool_kernel(const int* __restrict__ sse,
                      const float* __restrict__ bm,
                      float* __restrict__ out,
                      int num_groups, int ntotal)
{
    extern __shared__ char sm[];
    __half* As = (__half*)sm;                  // [buf][128][A_ST]
    __half* Bs = (__half*)(sm + A_BYTES);      // [buf][KC][B_ST]
    float*  smf = (float*)sm;                  // epilogue strips

    const int tid  = threadIdx.x;
    const int wid  = tid >> 5;
    const int wm   = wid >> 2;                 // 0..1
    const int wn   = wid & 3;                  // 0..3
    const int row0 = blockIdx.x * MROWS;
    const int rmax = min(MROWS, ntotal - row0);

    // Group containing row0 (binary search)
    int g0;
    {
        int lo = 0, hi = num_groups - 1;
        while (lo < hi) {
            const int mid = (lo + hi + 1) >> 1;
            if (sse[mid] <= row0) lo = mid; else hi = mid - 1;
        }
        g0 = lo;
    }

    auto issue_A = [&](int k0, int buf) {
        const uint32_t sb = smem_u32(As + buf * MROWS * A_ST);
        const __half* gp = g_hin + (size_t)row0 * KTOT + k0;
        #pragma unroll
        for (int q = 0; q < 5; q++) {
            const int u = tid + THREADS * q;   // 1280 units of 8 halfs
            const int r = u / 10, c = u % 10;  // 10 units per row (80 halfs)
            if (r < rmax)
                cp_async16(sb + (uint32_t)(r * A_ST + 8 * c) * 2,
                           gp + (size_t)r * KTOT + 8 * c);
        }
    };
    auto issue_B = [&](int k0, int n0, int buf) {
        const uint32_t sb = smem_u32(Bs + buf * KC * B_ST);
        const __half* gp = g_wm + (size_t)k0 * HDIM + n0;
        #pragma unroll
        for (int j = 0; j < 5; j++) {
            const int u = tid + THREADS * j;   // 1280 units of 8 halfs
            const int r = u >> 4, c = u & 15;  // 16 units per row (128 halfs)
            cp_async16(sb + (uint32_t)(r * B_ST + 8 * c) * 2,
                       gp + (size_t)r * HDIM + 8 * c);
        }
    };

    for (int pass = 0; pass < 4; pass++) {
        const int n0 = pass * NP;

        if (rmax < MROWS) {   // pad rows must be zero (tail tile only)
            for (int idx = tid; idx < A_BYTES / 16; idx += THREADS)
                reinterpret_cast<uint4*>(As)[idx] = make_uint4(0, 0, 0, 0);
        }
        __syncthreads();      // strips of previous pass fully read

        wmma::fragment<wmma::accumulator, 16, 16, 16, float> acc[4][2];
        #pragma unroll
        for (int i = 0; i < 4; i++) {
            wmma::fill_fragment(acc[i][0], 0.0f);
            wmma::fill_fragment(acc[i][1], 0.0f);
        }

        issue_A(0, 0);
        issue_B(0, n0, 0);
        CP_COMMIT();

        for (int i = 0; i < NCH; i++) {
            const int buf = i & 1;
            CP_WAIT0();
            __syncthreads();       // chunk i visible; buf^1 consumers done
            if (i + 1 < NCH) {     // copies for i+1 fly over the mma below
                issue_A((i + 1) * KC, buf ^ 1);
                issue_B((i + 1) * KC, n0, buf ^ 1);
                CP_COMMIT();
            }

            const __half* Ab = As + buf * MROWS * A_ST;
            const __half* Bb = Bs + buf * KC * B_ST;
            #pragma unroll
            for (int kk = 0; kk < KC; kk += 16) {
                wmma::fragment<wmma::matrix_a, 16, 16, 16, __half,
                               wmma::row_major> fa[4];
                #pragma unroll
                for (int i2 = 0; i2 < 4; i2++)
                    wmma::load_matrix_sync(fa[i2],
                        Ab + (64 * wm + 16 * i2) * A_ST + kk, A_ST);
                #pragma unroll
                for (int j = 0; j < 2; j++) {
                    wmma::fragment<wmma::matrix_b, 16, 16, 16, __half,
                                   wmma::row_major> fb;
                    wmma::load_matrix_sync(fb,
                        Bb + kk * B_ST + 32 * wn + 16 * j, B_ST);
                    #pragma unroll
                    for (int i2 = 0; i2 < 4; i2++)
                        wmma::mma_sync(acc[i2][j], fa[i2], fb, acc[i2][j]);
                }
            }
        }

        // ---- epilogue: strips, segment-wise column max (ILP-4) ------------
        __syncthreads();   // mainloop smem dead; strips may overwrite
        float* strip = smf + wn * (MROWS * S_ST);
        #pragma unroll
        for (int i = 0; i < 4; i++) {
            wmma::store_matrix_sync(strip + (64 * wm + 16 * i) * S_ST, acc[i][0],
                                    S_ST, wmma::mem_row_major);
            wmma::store_matrix_sync(strip + (64 * wm + 16 * i) * S_ST + 16,
                                    acc[i][1], S_ST, wmma::mem_row_major);
        }
        __syncthreads();

        if (tid < NP) {
            const int pcol = tid;
            const float* s = smf + (pcol >> 5) * (MROWS * S_ST) + (pcol & 31);
            const float bias = bm[n0 + pcol];
            const bool beg_cut = (sse[g0] < row0);
            int g = g0;
            int r = 0;
            while (r < rmax) {
                const int nxt = sse[g + 1] - row0;
                const int send = min(nxt, rmax);
                float m0 = -3.4e38f, m1 = -3.4e38f,
                      m2 = -3.4e38f, m3 = -3.4e38f;
                int rr = r;
                for (; rr + 3 < send; rr += 4) {
                    m0 = fmaxf(m0, s[(rr + 0) * S_ST]);
                    m1 = fmaxf(m1, s[(rr + 1) * S_ST]);
                    m2 = fmaxf(m2, s[(rr + 2) * S_ST]);
                    m3 = fmaxf(m3, s[(rr + 3) * S_ST]);
                }
                for (; rr < send; rr++)
                    m0 = fmaxf(m0, s[rr * S_ST]);
                const float mv = fmaxf(fmaxf(m0, m1), fmaxf(m2, m3));
                const float val = fmaxf(mv + bias, 0.f);
                float* dst = &out[(size_t)g * HDIM + n0 + pcol];
                const bool cut = (g == g0 && beg_cut) || (nxt > rmax);
                if (cut)
                    atomicMax((unsigned*)dst, __float_as_uint(val));
                else
                    *dst = val;
                g++;
                r = send;
            }
        }
        __syncthreads();   // strips read before next pass restages smem
    }
}

extern "C" void kernel_launch(void* const* d_in, const int* in_sizes, int n_in,
                              void* d_out, int out_size)
{
    const float* hist_enc = (const float*)d_in[0];
    const float* hist_pos = (const float*)d_in[1];
    const int*   sse      = (const int*)d_in[2];
    const float* Ws       = (const float*)d_in[3];
    const float* bs       = (const float*)d_in[4];
    const float* Wm       = (const float*)d_in[5];
    const float* bm       = (const float*)d_in[6];
    float* out            = (float*)d_out;

    const int num_groups = in_sizes[2] - 1;
    const int ntotal     = in_sizes[0] / HDIM;
    const int grid       = (ntotal + MROWS - 1) / MROWS;

    cudaFuncSetAttribute(gemm_pool_kernel,
                         cudaFuncAttributeMaxDynamicSharedMemorySize,
                         SMEM_BYTES);

    init_out_kernel<<<(out_size / 4 + 255) / 256, 256>>>(out);
    conv_wm_kernel<<<(KTOT * HDIM / 4) / 256, 256>>>(Wm);
    build_hin_kernel<<<num_groups, 256>>>(hist_enc, hist_pos, sse, Ws, bs);
    gemm_pool_kernel<<<grid, THREADS, SMEM_BYTES>>>(sse, bm, out,
                                                    num_groups, ntotal);
}